// round 9
// baseline (speedup 1.0000x reference)
#include <cuda_runtime.h>
#include <cstdint>

// Pendulum2 constrained-dynamics RHS, closed form — R4 body (best measured:
// 17.9-18.1us kernel / 21.0us harness, rel_err 1.3e-7, ~7.4 TB/s aggregate).
// Probe: block=128 for finer CTA packing (occ 74% at block=256 despite no
// resource limit -> CTA-granularity quantization; 4-warp CTAs should pack
// to ~90-100% occ and cover the residual DRAM-latency exposure for free).
//
// Shape: one row (32B) per thread, Blackwell 256-bit ld/st -> warp-dense
// requests; 25 regs. Rejected by measurement: thicker threads (R2/R3/R6),
// cache hints (R2/R5), block 512 (R7).
//
// Math (M0=M1=10, G=10), closed-form replacement of the jacfwd/vmap/solve:
//   det' = 2 s1 s2 - c^2 = s1 s2 + u^2  (u = x0 dy - x1 dx; cancellation-free)
//   R1 = -20 x1 + 2|v01|^2 ; R2 = 2|dv|^2  (gravity row-2 term cancels)
//   lam = 2.5 * adj([[s1,c],[c,2s2]]) R / det' ;  a = (F - phi_q^T lam)/10

__global__ void __launch_bounds__(128)
pendulum2_kernel(const float* __restrict__ in, float* __restrict__ out, int bs)
{
    int i = blockIdx.x * blockDim.x + threadIdx.x;
    if (i >= bs) return;

    const float* p = in + 8u * (uint32_t)i;
    uint32_t r0, r1, r2, r3, r4, r5, r6, r7;
    asm("ld.global.v8.b32 {%0,%1,%2,%3,%4,%5,%6,%7}, [%8];"
        : "=r"(r0), "=r"(r1), "=r"(r2), "=r"(r3),
          "=r"(r4), "=r"(r5), "=r"(r6), "=r"(r7)
        : "l"(p));

    float x0 = __uint_as_float(r0), x1 = __uint_as_float(r1);
    float x2 = __uint_as_float(r2), x3 = __uint_as_float(r3);
    float v0 = __uint_as_float(r4), v1 = __uint_as_float(r5);
    float v2 = __uint_as_float(r6), v3 = __uint_as_float(r7);

    float dx  = x0 - x2;
    float dy  = x1 - x3;
    float dv0 = v0 - v2;
    float dv1 = v1 - v3;

    float s1 = fmaf(x0, x0, x1 * x1);
    float s2 = fmaf(dx, dx, dy * dy);
    float c  = fmaf(x0, dx, x1 * dy);
    float u  = fmaf(x0, dy, -(x1 * dx));

    float R1 = fmaf(2.0f, fmaf(v0, v0, v1 * v1), -20.0f * x1);
    float R2 = 2.0f * fmaf(dv0, dv0, dv1 * dv1);

    float det = fmaf(s1, s2, u * u);   // = 2*s1*s2 - c^2, stable form
    float inv = 2.5f / det;

    float lam1 = fmaf(2.0f * s2, R1, -(c * R2)) * inv;
    float lam2 = fmaf(s1, R2, -(c * R1)) * inv;

    float a0 = -0.2f * fmaf(x0, lam1, dx * lam2);
    float a1 = fmaf(-0.2f, fmaf(x1, lam1, dy * lam2), -10.0f);
    float a2 = 0.2f * (dx * lam2);
    float a3 = fmaf(0.2f, dy * lam2, -10.0f);

    float* q = out + 8u * (uint32_t)i;
    asm volatile("st.global.v8.b32 [%0], {%1,%2,%3,%4,%5,%6,%7,%8};"
                 :: "l"(q),
                    "r"(__float_as_uint(v0)), "r"(__float_as_uint(v1)),
                    "r"(__float_as_uint(v2)), "r"(__float_as_uint(v3)),
                    "r"(__float_as_uint(a0)), "r"(__float_as_uint(a1)),
                    "r"(__float_as_uint(a2)), "r"(__float_as_uint(a3))
                 : "memory");
}

extern "C" void kernel_launch(void* const* d_in, const int* in_sizes, int n_in,
                              void* d_out, int out_size)
{
    // inputs (metadata order): t (1,), coords (bs, 8)
    const float* coords = (const float*)d_in[1];
    int bs = in_sizes[1] / 8;

    int threads = 128;
    int blocks  = (bs + threads - 1) / threads;
    pendulum2_kernel<<<blocks, threads>>>(coords, (float*)d_out, bs);
}